// round 2
// baseline (speedup 1.0000x reference)
#include <cuda_runtime.h>
#include <cstddef>

#define N_NODES 100000
#define N_EDGES 1600000

// ---------------- scratch (static device arrays; no cudaMalloc) ------------
__device__ float g_c1[(size_t)N_NODES * 256];  // [self(128) | neigh(128)] layer1
__device__ float g_c2[(size_t)N_NODES * 128];  // [self(64)  | neigh(64) ] layer2
__device__ int   g_deg[N_NODES];
__device__ int   g_off[N_NODES + 1];
__device__ int   g_cur[N_NODES];
__device__ int   g_ssrc[N_EDGES];

// ---------------- CSR build ------------------------------------------------
__global__ void zero_deg_kernel() {
    int i = blockIdx.x * blockDim.x + threadIdx.x;
    if (i < N_NODES) g_deg[i] = 0;
}

__global__ void count_deg_kernel(const int* __restrict__ dst) {
    int e = blockIdx.x * blockDim.x + threadIdx.x;
    if (e < N_EDGES) atomicAdd(&g_deg[dst[e]], 1);
}

// single-block exclusive scan over 100k degrees (1024 threads, chunked)
__global__ void scan_offsets_kernel() {
    __shared__ int part[1024];
    const int tid = threadIdx.x;
    const int CH = (N_NODES + 1023) / 1024;  // 98
    int beg = tid * CH;
    int end = beg + CH; if (end > N_NODES) end = N_NODES;
    if (beg > N_NODES) beg = N_NODES;

    int s = 0;
    for (int i = beg; i < end; i++) s += g_deg[i];
    part[tid] = s;
    __syncthreads();
    for (int off = 1; off < 1024; off <<= 1) {
        int v = (tid >= off) ? part[tid - off] : 0;
        __syncthreads();
        part[tid] += v;
        __syncthreads();
    }
    int run = (tid == 0) ? 0 : part[tid - 1];  // exclusive prefix
    for (int i = beg; i < end; i++) {
        g_off[i] = run;
        g_cur[i] = run;
        run += g_deg[i];
    }
    if (tid == 1023) g_off[N_NODES] = run;
}

__global__ void fill_csr_kernel(const int* __restrict__ src,
                                const int* __restrict__ dst) {
    int e = blockIdx.x * blockDim.x + threadIdx.x;
    if (e < N_EDGES) {
        int p = atomicAdd(&g_cur[dst[e]], 1);
        g_ssrc[p] = src[e];
    }
}

// ---------------- fused dual-weight SGEMM ----------------------------------
// C[M, 2*n0] = A[M,128] @ [B0 | B1]  (bias added to cols < n0 only)
// BM=128 BN=128 BK=8, 256 threads, 8x8 register tile per thread.
__global__ __launch_bounds__(256)
void sgemm_dual(const float* __restrict__ A,
                const float* __restrict__ B0,
                const float* __restrict__ B1,
                const float* __restrict__ bias,   // length n0
                float* __restrict__ C,
                int M, int n0) {
    constexpr int BM = 128, BN = 128, BK = 8, TM = 8, TN = 8, K = 128;
    const int N = 2 * n0;
    __shared__ float As[BK][BM];
    __shared__ float Bs[BK][BN];

    const int tid  = threadIdx.x;
    const int brow = blockIdx.x * BM;
    const int bcol = blockIdx.y * BN;

    // A tile: 128 rows x 8 cols = 256 float4, one per thread (stored transposed)
    const int aRow = tid >> 1;
    const int aCol = (tid & 1) * 4;
    // B tile: 8 rows x 128 cols = 256 float4, one per thread
    const int bRow  = tid >> 5;         // 0..7
    const int bColL = (tid & 31) * 4;   // 0..124

    const int tRow = (tid >> 4) * TM;   // 0..120
    const int tCol = (tid & 15) * TN;   // 0..120

    // per-thread B source column (n0 is a multiple of 4, no float4 straddle)
    const int gcol = bcol + bColL;
    const float* bsrc = (gcol < n0) ? (B0 + gcol) : (B1 + (gcol - n0));

    const bool arow_ok = (brow + aRow) < M;
    const float* aptr = A + (size_t)(brow + aRow) * K + aCol;

    float acc[TM][TN] = {};

    for (int k0 = 0; k0 < K; k0 += BK) {
        float4 av = make_float4(0.f, 0.f, 0.f, 0.f);
        if (arow_ok) av = *reinterpret_cast<const float4*>(aptr + k0);
        As[aCol + 0][aRow] = av.x;
        As[aCol + 1][aRow] = av.y;
        As[aCol + 2][aRow] = av.z;
        As[aCol + 3][aRow] = av.w;

        float4 bv = *reinterpret_cast<const float4*>(bsrc + (size_t)(k0 + bRow) * n0);
        *reinterpret_cast<float4*>(&Bs[bRow][bColL]) = bv;
        __syncthreads();

#pragma unroll
        for (int kk = 0; kk < BK; kk++) {
            float4 m0 = *reinterpret_cast<const float4*>(&As[kk][tRow]);
            float4 m1 = *reinterpret_cast<const float4*>(&As[kk][tRow + 4]);
            float4 q0 = *reinterpret_cast<const float4*>(&Bs[kk][tCol]);
            float4 q1 = *reinterpret_cast<const float4*>(&Bs[kk][tCol + 4]);
            float rm[TM] = {m0.x, m0.y, m0.z, m0.w, m1.x, m1.y, m1.z, m1.w};
            float rn[TN] = {q0.x, q0.y, q0.z, q0.w, q1.x, q1.y, q1.z, q1.w};
#pragma unroll
            for (int i = 0; i < TM; i++)
#pragma unroll
                for (int j = 0; j < TN; j++)
                    acc[i][j] += rm[i] * rn[j];
        }
        __syncthreads();
    }

    // bias (cols >= n0 get 0); tCol aligned to 8, n0 multiple of 8 -> no split
    float bvreg[TN];
#pragma unroll
    for (int j = 0; j < TN; j++) {
        int gc = bcol + tCol + j;
        bvreg[j] = (gc < n0) ? bias[gc] : 0.f;
    }

#pragma unroll
    for (int i = 0; i < TM; i++) {
        int r = brow + tRow + i;
        if (r >= M) continue;
        float* crow = C + (size_t)r * N + bcol + tCol;
        float4 o0, o1;
        o0.x = acc[i][0] + bvreg[0];
        o0.y = acc[i][1] + bvreg[1];
        o0.z = acc[i][2] + bvreg[2];
        o0.w = acc[i][3] + bvreg[3];
        o1.x = acc[i][4] + bvreg[4];
        o1.y = acc[i][5] + bvreg[5];
        o1.z = acc[i][6] + bvreg[6];
        o1.w = acc[i][7] + bvreg[7];
        *reinterpret_cast<float4*>(crow)     = o0;
        *reinterpret_cast<float4*>(crow + 4) = o1;
    }
}

// ---------------- layer-1 gather+combine: warp per dst node (D=128) --------
// C1 row layout: [self 0..127 | neigh 128..255]
__global__ __launch_bounds__(256)
void gather_combine1(const float* __restrict__ C1,
                     float* __restrict__ out_h1,
                     float* __restrict__ out_h1r) {
    int warp = (blockIdx.x * blockDim.x + threadIdx.x) >> 5;
    int lane = threadIdx.x & 31;
    if (warp >= N_NODES) return;
    const int n   = warp;
    const int beg = g_off[n];
    const int end = g_off[n + 1];

    float4 acc = make_float4(0.f, 0.f, 0.f, 0.f);
    int e = beg;
    for (; e + 1 < end; e += 2) {
        int s0 = g_ssrc[e];
        int s1 = g_ssrc[e + 1];
        float4 v0 = *reinterpret_cast<const float4*>(C1 + (size_t)s0 * 256 + 128 + lane * 4);
        float4 v1 = *reinterpret_cast<const float4*>(C1 + (size_t)s1 * 256 + 128 + lane * 4);
        acc.x += v0.x + v1.x; acc.y += v0.y + v1.y;
        acc.z += v0.z + v1.z; acc.w += v0.w + v1.w;
    }
    if (e < end) {
        int s0 = g_ssrc[e];
        float4 v0 = *reinterpret_cast<const float4*>(C1 + (size_t)s0 * 256 + 128 + lane * 4);
        acc.x += v0.x; acc.y += v0.y; acc.z += v0.z; acc.w += v0.w;
    }
    float deg = (float)(end - beg);
    float inv = 1.0f / fmaxf(deg, 1.0f);
    float4 hs = *reinterpret_cast<const float4*>(C1 + (size_t)n * 256 + lane * 4);
    float4 h1;
    h1.x = hs.x + acc.x * inv;
    h1.y = hs.y + acc.y * inv;
    h1.z = hs.z + acc.z * inv;
    h1.w = hs.w + acc.w * inv;
    *reinterpret_cast<float4*>(out_h1 + (size_t)n * 128 + lane * 4) = h1;
    float4 r;
    r.x = fmaxf(h1.x, 0.f); r.y = fmaxf(h1.y, 0.f);
    r.z = fmaxf(h1.z, 0.f); r.w = fmaxf(h1.w, 0.f);
    *reinterpret_cast<float4*>(out_h1r + (size_t)n * 128 + lane * 4) = r;
}

// ---------------- layer-2 gather+combine: warp per dst node (D=64) ---------
// C2 row layout: [self 0..63 | neigh 64..127]
__global__ __launch_bounds__(256)
void gather_combine2(const float* __restrict__ C2,
                     float* __restrict__ out_a,
                     float* __restrict__ out_b) {
    int warp = (blockIdx.x * blockDim.x + threadIdx.x) >> 5;
    int lane = threadIdx.x & 31;
    if (warp >= N_NODES) return;
    const int n   = warp;
    const int beg = g_off[n];
    const int end = g_off[n + 1];

    float2 acc = make_float2(0.f, 0.f);
    int e = beg;
    for (; e + 1 < end; e += 2) {
        int s0 = g_ssrc[e];
        int s1 = g_ssrc[e + 1];
        float2 v0 = *reinterpret_cast<const float2*>(C2 + (size_t)s0 * 128 + 64 + lane * 2);
        float2 v1 = *reinterpret_cast<const float2*>(C2 + (size_t)s1 * 128 + 64 + lane * 2);
        acc.x += v0.x + v1.x; acc.y += v0.y + v1.y;
    }
    if (e < end) {
        int s0 = g_ssrc[e];
        float2 v0 = *reinterpret_cast<const float2*>(C2 + (size_t)s0 * 128 + 64 + lane * 2);
        acc.x += v0.x; acc.y += v0.y;
    }
    float deg = (float)(end - beg);
    float inv = 1.0f / fmaxf(deg, 1.0f);
    float2 hs = *reinterpret_cast<const float2*>(C2 + (size_t)n * 128 + lane * 2);
    float2 h2;
    h2.x = hs.x + acc.x * inv;
    h2.y = hs.y + acc.y * inv;
    *reinterpret_cast<float2*>(out_a + (size_t)n * 64 + lane * 2) = h2;
    *reinterpret_cast<float2*>(out_b + (size_t)n * 64 + lane * 2) = h2;
}

// ---------------- launch ---------------------------------------------------
extern "C" void kernel_launch(void* const* d_in, const int* in_sizes, int n_in,
                              void* d_out, int out_size) {
    const float* x        = (const float*)d_in[0];
    const float* W_self1  = (const float*)d_in[1];
    const float* W_neigh1 = (const float*)d_in[2];
    const float* b1       = (const float*)d_in[3];
    const float* W_self2  = (const float*)d_in[4];
    const float* W_neigh2 = (const float*)d_in[5];
    const float* b2       = (const float*)d_in[6];
    const int*   src      = (const int*)d_in[7];
    const int*   dst      = (const int*)d_in[8];

    float* out = (float*)d_out;
    // reference returns (h2, h1, h1_relu, h2) flattened in order
    float* out_h2a = out;                                      // 100000*64
    float* out_h1  = out + (size_t)N_NODES * 64;               // 100000*128
    float* out_h1r = out + (size_t)N_NODES * (64 + 128);       // 100000*128
    float* out_h2b = out + (size_t)N_NODES * (64 + 128 + 128); // 100000*64

    float* c1 = nullptr, *c2 = nullptr;
    cudaGetSymbolAddress((void**)&c1, g_c1);
    cudaGetSymbolAddress((void**)&c2, g_c2);

    // --- CSR build (shared by both layers) ---
    zero_deg_kernel<<<(N_NODES + 255) / 256, 256>>>();
    count_deg_kernel<<<(N_EDGES + 255) / 256, 256>>>(dst);
    scan_offsets_kernel<<<1, 1024>>>();
    fill_csr_kernel<<<(N_EDGES + 255) / 256, 256>>>(src, dst);

    // --- layer 1 fused GEMM: C1 = x @ [W_self1 | W_neigh1] (+b1 on self) ---
    dim3 g1((N_NODES + 127) / 128, 2);
    sgemm_dual<<<g1, 256>>>(x, W_self1, W_neigh1, b1, c1, N_NODES, 128);

    int gblocks = (N_NODES * 32 + 255) / 256;  // one warp per node
    gather_combine1<<<gblocks, 256>>>(c1, out_h1, out_h1r);

    // --- layer 2 fused GEMM on h1_relu ---
    dim3 g2((N_NODES + 127) / 128, 1);
    sgemm_dual<<<g2, 256>>>(out_h1r, W_self2, W_neigh2, b2, c2, N_NODES, 64);

    gather_combine2<<<gblocks, 256>>>(c2, out_h2a, out_h2b);
}

// round 3
// speedup vs baseline: 1.0282x; 1.0282x over previous
#include <cuda_runtime.h>
#include <cstddef>
#include <cstdint>

#define N_NODES 100000
#define N_EDGES 1600000

// ---------------- scratch (static device arrays; no cudaMalloc) ------------
__device__ float g_t1[(size_t)N_NODES * 128];     // x @ W_neigh1        (51MB, L2-resident for gather1)
__device__ float g_hself1[(size_t)N_NODES * 128]; // x @ W_self1 + b1
__device__ float g_t2[(size_t)N_NODES * 64];      // h1_relu @ W_neigh2  (25MB, L2-resident for gather2)
__device__ float g_hself2[(size_t)N_NODES * 64];  // h1_relu @ W_self2 + b2
__device__ int   g_deg[N_NODES];
__device__ int   g_off[N_NODES + 1];
__device__ int   g_cur[N_NODES];
__device__ int   g_ssrc[N_EDGES];

// ---------------- CSR build ------------------------------------------------
__global__ void zero_deg_kernel() {
    int i = blockIdx.x * blockDim.x + threadIdx.x;
    if (i < N_NODES) g_deg[i] = 0;
}

__global__ void count_deg_kernel(const int* __restrict__ dst) {
    int e = blockIdx.x * blockDim.x + threadIdx.x;
    if (e < N_EDGES) atomicAdd(&g_deg[dst[e]], 1);
}

// single-block exclusive scan over 100k degrees (1024 threads, chunked)
__global__ void scan_offsets_kernel() {
    __shared__ int part[1024];
    const int tid = threadIdx.x;
    const int CH = (N_NODES + 1023) / 1024;  // 98
    int beg = tid * CH;
    int end = beg + CH; if (end > N_NODES) end = N_NODES;
    if (beg > N_NODES) beg = N_NODES;

    int s = 0;
    for (int i = beg; i < end; i++) s += g_deg[i];
    part[tid] = s;
    __syncthreads();
    for (int off = 1; off < 1024; off <<= 1) {
        int v = (tid >= off) ? part[tid - off] : 0;
        __syncthreads();
        part[tid] += v;
        __syncthreads();
    }
    int run = (tid == 0) ? 0 : part[tid - 1];  // exclusive prefix
    for (int i = beg; i < end; i++) {
        g_off[i] = run;
        g_cur[i] = run;
        run += g_deg[i];
    }
    if (tid == 1023) g_off[N_NODES] = run;
}

__global__ void fill_csr_kernel(const int* __restrict__ src,
                                const int* __restrict__ dst) {
    int e = blockIdx.x * blockDim.x + threadIdx.x;
    if (e < N_EDGES) {
        int p = atomicAdd(&g_cur[dst[e]], 1);
        g_ssrc[p] = src[e];
    }
}

// ---------------- 3xTF32 tensor-core dual-output GEMM ----------------------
// Computes C[M, 2*n0] = A[M,128] @ [B0 | B1], writing cols < n0 to out0
// (+bias) and cols >= n0 to out1. 3x-split tf32: a=ah+al, b=bh+bl,
// D += ah*bh + ah*bl + al*bh  (error ~1e-7, fp32-equivalent).
// BM=128, BN=128, BK=16; 256 threads = 8 warps as 4(M)x2(N), warp tile 32x64.

__device__ __forceinline__ float tf32_rn(float v) {
    uint32_t o;
    asm("cvt.rna.tf32.f32 %0, %1;" : "=r"(o) : "f"(v));
    return __uint_as_float(o);
}

__device__ __forceinline__ void mma_tf32(float* c,
                                         uint32_t a0, uint32_t a1, uint32_t a2, uint32_t a3,
                                         uint32_t b0, uint32_t b1) {
    asm volatile(
        "mma.sync.aligned.m16n8k8.row.col.f32.tf32.tf32.f32 "
        "{%0,%1,%2,%3}, {%4,%5,%6,%7}, {%8,%9}, {%0,%1,%2,%3};\n"
        : "+f"(c[0]), "+f"(c[1]), "+f"(c[2]), "+f"(c[3])
        : "r"(a0), "r"(a1), "r"(a2), "r"(a3), "r"(b0), "r"(b1));
}

__global__ __launch_bounds__(256, 2)
void tf32_dual_gemm(const float* __restrict__ A,
                    const float* __restrict__ B0,
                    const float* __restrict__ B1,
                    const float* __restrict__ bias,   // applied to out0 cols
                    float* __restrict__ out0,
                    float* __restrict__ out1,
                    int M, int n0) {
    constexpr int BM = 128, BN = 128, BK = 16, K = 128;
    __shared__ float2 As2[BK][BM + 2];   // {hi, lo} per element, [k][m]
    __shared__ float2 Bs2[BK][BN + 2];   // {hi, lo} per element, [k][n]

    const int tid  = threadIdx.x;
    const int lane = tid & 31;
    const int warp = tid >> 5;
    const int g    = lane >> 2;    // groupID
    const int tg   = lane & 3;     // thread-in-group
    const int warpM = (warp >> 1) * 32;  // 0,32,64,96
    const int warpN = (warp & 1) * 64;   // 0,64
    const int brow = blockIdx.x * BM;
    const int bcol = blockIdx.y * BN;

    // A global load mapping: row = tid>>1, col half = (tid&1)*8 (2x float4)
    const int aRow = tid >> 1;
    const int aCol = (tid & 1) * 8;
    const bool aOK = (brow + aRow) < M;
    const float* aBase = A + (size_t)(brow + aRow) * K + aCol;

    // B global load mapping: k = tid>>4, colbase = (tid&15)*8 (2x float4)
    const int bK = tid >> 4;
    const int bC = (tid & 15) * 8;
    const int bGC = bcol + bC;
    const float* bHalf = (bGC < n0) ? B0 : B1;
    const int   bCol   = (bGC < n0) ? bGC : (bGC - n0);

    float acc[2][8][4];
#pragma unroll
    for (int mt = 0; mt < 2; mt++)
#pragma unroll
        for (int nt = 0; nt < 8; nt++)
#pragma unroll
            for (int q = 0; q < 4; q++) acc[mt][nt][q] = 0.f;

    for (int k0 = 0; k0 < K; k0 += BK) {
        // ---- stage A chunk (convert fp32 -> tf32 hi/lo) ----
#pragma unroll
        for (int h = 0; h < 2; h++) {
            float4 v = make_float4(0.f, 0.f, 0.f, 0.f);
            if (aOK) v = *reinterpret_cast<const float4*>(aBase + k0 + h * 4);
            float vv[4] = {v.x, v.y, v.z, v.w};
#pragma unroll
            for (int j = 0; j < 4; j++) {
                float hi = tf32_rn(vv[j]);
                float lo = tf32_rn(vv[j] - hi);
                As2[aCol + h * 4 + j][aRow] = make_float2(hi, lo);
            }
        }
        // ---- stage B chunk ----
#pragma unroll
        for (int h = 0; h < 2; h++) {
            float4 v = *reinterpret_cast<const float4*>(
                bHalf + (size_t)(k0 + bK) * n0 + bCol + h * 4);
            float vv[4] = {v.x, v.y, v.z, v.w};
#pragma unroll
            for (int j = 0; j < 4; j++) {
                float hi = tf32_rn(vv[j]);
                float lo = tf32_rn(vv[j] - hi);
                Bs2[bK][bC + h * 4 + j] = make_float2(hi, lo);
            }
        }
        __syncthreads();

        // ---- compute: 2 k-steps of 8 ----
#pragma unroll
        for (int kk = 0; kk < BK; kk += 8) {
            float2 af[2][4];
#pragma unroll
            for (int mt = 0; mt < 2; mt++) {
                int m = warpM + mt * 16 + g;
                af[mt][0] = As2[kk + tg][m];
                af[mt][1] = As2[kk + tg][m + 8];
                af[mt][2] = As2[kk + tg + 4][m];
                af[mt][3] = As2[kk + tg + 4][m + 8];
            }
#pragma unroll
            for (int nt = 0; nt < 8; nt++) {
                int n = warpN + nt * 8 + g;
                float2 bf0 = Bs2[kk + tg][n];
                float2 bf1 = Bs2[kk + tg + 4][n];
                uint32_t bh0 = __float_as_uint(bf0.x), bl0 = __float_as_uint(bf0.y);
                uint32_t bh1 = __float_as_uint(bf1.x), bl1 = __float_as_uint(bf1.y);
#pragma unroll
                for (int mt = 0; mt < 2; mt++) {
                    uint32_t ah0 = __float_as_uint(af[mt][0].x);
                    uint32_t ah1 = __float_as_uint(af[mt][1].x);
                    uint32_t ah2 = __float_as_uint(af[mt][2].x);
                    uint32_t ah3 = __float_as_uint(af[mt][3].x);
                    uint32_t al0 = __float_as_uint(af[mt][0].y);
                    uint32_t al1 = __float_as_uint(af[mt][1].y);
                    uint32_t al2 = __float_as_uint(af[mt][2].y);
                    uint32_t al3 = __float_as_uint(af[mt][3].y);
                    mma_tf32(acc[mt][nt], ah0, ah1, ah2, ah3, bh0, bh1);
                    mma_tf32(acc[mt][nt], ah0, ah1, ah2, ah3, bl0, bl1);
                    mma_tf32(acc[mt][nt], al0, al1, al2, al3, bh0, bh1);
                }
            }
        }
        __syncthreads();
    }

    // ---- epilogue ----
#pragma unroll
    for (int mt = 0; mt < 2; mt++) {
#pragma unroll
        for (int nt = 0; nt < 8; nt++) {
            int gcol = bcol + warpN + nt * 8 + 2 * tg;
            float* base; int cc; float bb0 = 0.f, bb1 = 0.f;
            if (gcol < n0) {
                base = out0; cc = gcol;
                if (bias) { bb0 = bias[gcol]; bb1 = bias[gcol + 1]; }
            } else {
                base = out1; cc = gcol - n0;
            }
            int r0 = brow + warpM + mt * 16 + g;
            int r1 = r0 + 8;
            if (r0 < M) {
                float2 o = make_float2(acc[mt][nt][0] + bb0, acc[mt][nt][1] + bb1);
                *reinterpret_cast<float2*>(base + (size_t)r0 * n0 + cc) = o;
            }
            if (r1 < M) {
                float2 o = make_float2(acc[mt][nt][2] + bb0, acc[mt][nt][3] + bb1);
                *reinterpret_cast<float2*>(base + (size_t)r1 * n0 + cc) = o;
            }
        }
    }
}

// ---------------- layer-1 gather+combine: warp per dst node (D=128) --------
__global__ __launch_bounds__(256)
void gather_combine1(const float* __restrict__ hself,
                     const float* __restrict__ t,
                     float* __restrict__ out_h1,
                     float* __restrict__ out_h1r) {
    int warp = (blockIdx.x * blockDim.x + threadIdx.x) >> 5;
    int lane = threadIdx.x & 31;
    if (warp >= N_NODES) return;
    const int n   = warp;
    const int beg = g_off[n];
    const int end = g_off[n + 1];

    float4 acc = make_float4(0.f, 0.f, 0.f, 0.f);
    int e = beg;
    for (; e + 1 < end; e += 2) {
        int s0 = g_ssrc[e];
        int s1 = g_ssrc[e + 1];
        float4 v0 = *reinterpret_cast<const float4*>(t + (size_t)s0 * 128 + lane * 4);
        float4 v1 = *reinterpret_cast<const float4*>(t + (size_t)s1 * 128 + lane * 4);
        acc.x += v0.x + v1.x; acc.y += v0.y + v1.y;
        acc.z += v0.z + v1.z; acc.w += v0.w + v1.w;
    }
    if (e < end) {
        int s0 = g_ssrc[e];
        float4 v0 = *reinterpret_cast<const float4*>(t + (size_t)s0 * 128 + lane * 4);
        acc.x += v0.x; acc.y += v0.y; acc.z += v0.z; acc.w += v0.w;
    }
    float deg = (float)(end - beg);
    float inv = 1.0f / fmaxf(deg, 1.0f);
    float4 hs = *reinterpret_cast<const float4*>(hself + (size_t)n * 128 + lane * 4);
    float4 h1;
    h1.x = hs.x + acc.x * inv;
    h1.y = hs.y + acc.y * inv;
    h1.z = hs.z + acc.z * inv;
    h1.w = hs.w + acc.w * inv;
    *reinterpret_cast<float4*>(out_h1 + (size_t)n * 128 + lane * 4) = h1;
    float4 r;
    r.x = fmaxf(h1.x, 0.f); r.y = fmaxf(h1.y, 0.f);
    r.z = fmaxf(h1.z, 0.f); r.w = fmaxf(h1.w, 0.f);
    *reinterpret_cast<float4*>(out_h1r + (size_t)n * 128 + lane * 4) = r;
}

// ---------------- layer-2 gather+combine: warp per dst node (D=64) ---------
__global__ __launch_bounds__(256)
void gather_combine2(const float* __restrict__ hself,
                     const float* __restrict__ t,
                     float* __restrict__ out_a,
                     float* __restrict__ out_b) {
    int warp = (blockIdx.x * blockDim.x + threadIdx.x) >> 5;
    int lane = threadIdx.x & 31;
    if (warp >= N_NODES) return;
    const int n   = warp;
    const int beg = g_off[n];
    const int end = g_off[n + 1];

    float2 acc = make_float2(0.f, 0.f);
    int e = beg;
    for (; e + 1 < end; e += 2) {
        int s0 = g_ssrc[e];
        int s1 = g_ssrc[e + 1];
        float2 v0 = *reinterpret_cast<const float2*>(t + (size_t)s0 * 64 + lane * 2);
        float2 v1 = *reinterpret_cast<const float2*>(t + (size_t)s1 * 64 + lane * 2);
        acc.x += v0.x + v1.x; acc.y += v0.y + v1.y;
    }
    if (e < end) {
        int s0 = g_ssrc[e];
        float2 v0 = *reinterpret_cast<const float2*>(t + (size_t)s0 * 64 + lane * 2);
        acc.x += v0.x; acc.y += v0.y;
    }
    float deg = (float)(end - beg);
    float inv = 1.0f / fmaxf(deg, 1.0f);
    float2 hs = *reinterpret_cast<const float2*>(hself + (size_t)n * 64 + lane * 2);
    float2 h2;
    h2.x = hs.x + acc.x * inv;
    h2.y = hs.y + acc.y * inv;
    *reinterpret_cast<float2*>(out_a + (size_t)n * 64 + lane * 2) = h2;
    *reinterpret_cast<float2*>(out_b + (size_t)n * 64 + lane * 2) = h2;
}

// ---------------- launch ---------------------------------------------------
extern "C" void kernel_launch(void* const* d_in, const int* in_sizes, int n_in,
                              void* d_out, int out_size) {
    const float* x        = (const float*)d_in[0];
    const float* W_self1  = (const float*)d_in[1];
    const float* W_neigh1 = (const float*)d_in[2];
    const float* b1       = (const float*)d_in[3];
    const float* W_self2  = (const float*)d_in[4];
    const float* W_neigh2 = (const float*)d_in[5];
    const float* b2       = (const float*)d_in[6];
    const int*   src      = (const int*)d_in[7];
    const int*   dst      = (const int*)d_in[8];

    float* out = (float*)d_out;
    // reference returns (h2, h1, h1_relu, h2) flattened in order
    float* out_h2a = out;                                      // 100000*64
    float* out_h1  = out + (size_t)N_NODES * 64;               // 100000*128
    float* out_h1r = out + (size_t)N_NODES * (64 + 128);       // 100000*128
    float* out_h2b = out + (size_t)N_NODES * (64 + 128 + 128); // 100000*64

    float* t1 = nullptr, *hs1 = nullptr, *t2 = nullptr, *hs2 = nullptr;
    cudaGetSymbolAddress((void**)&t1,  g_t1);
    cudaGetSymbolAddress((void**)&hs1, g_hself1);
    cudaGetSymbolAddress((void**)&t2,  g_t2);
    cudaGetSymbolAddress((void**)&hs2, g_hself2);

    // --- CSR build (shared by both layers) ---
    zero_deg_kernel<<<(N_NODES + 255) / 256, 256>>>();
    count_deg_kernel<<<(N_EDGES + 255) / 256, 256>>>(dst);
    scan_offsets_kernel<<<1, 1024>>>();
    fill_csr_kernel<<<(N_EDGES + 255) / 256, 256>>>(src, dst);

    // --- layer 1 GEMM (tensor cores): hs1 = x@W_self1+b1 ; t1 = x@W_neigh1 ---
    dim3 g1((N_NODES + 127) / 128, 2);   // y=0 -> self cols, y=1 -> neigh cols
    tf32_dual_gemm<<<g1, 256>>>(x, W_self1, W_neigh1, b1, hs1, t1, N_NODES, 128);

    int gblocks = (N_NODES * 32 + 255) / 256;  // one warp per node
    gather_combine1<<<gblocks, 256>>>(hs1, t1, out_h1, out_h1r);

    // --- layer 2 GEMM on h1_relu: hs2 = h1r@W_self2+b2 ; t2 = h1r@W_neigh2 ---
    dim3 g2((N_NODES + 127) / 128, 1);   // 128 cols span both 64-wide halves
    tf32_dual_gemm<<<g2, 256>>>(out_h1r, W_self2, W_neigh2, b2, hs2, t2, N_NODES, 64);

    gather_combine2<<<gblocks, 256>>>(hs2, t2, out_h2a, out_h2b);
}